// round 14
// baseline (speedup 1.0000x reference)
#include <cuda_runtime.h>
#include <cuda_fp16.h>

// ---------------------------------------------------------------------------
#define B_ROWS   2048
#define NFEAT    128
#define NCOLS    256
#define NB_ROWS  264        // 256 V|T cols + 8 scal cols (vv,tt,vt,W,1,0,0,0)
#define K_TOTAL  50000
#define KPAD     50560      // multiple of 64, zero padded
#define U_DIM    10000
#define X_DIM    20000
#define KSTEP    64
#define STAGE_SZ 50176      // Ah 16K | B 33K (264 rows x 128B)
#define SMEM_DYN 151552     // 3 stages + 1KB align slack
#define NTHREADS 512

// ---------------------------------------------------------------------------
__device__ unsigned short BT16[(size_t)NB_ROWS * KPAD];  // fp16, K-major
__device__ float g_acc[(size_t)3 * B_ROWS * NCOLS];
__device__ float g_scal[3 * B_ROWS * 8];

// ---------------------------------------------------------------------------
__device__ __forceinline__ unsigned smem_u32(const void* p) {
    unsigned r;
    asm("{ .reg .u64 t; cvta.to.shared.u64 t, %1; cvt.u32.u64 %0, t; }" : "=r"(r) : "l"(p));
    return r;
}
__device__ __forceinline__ unsigned pack2h(float f0, float f1) {
    return (unsigned)__half_as_ushort(__float2half_rn(f0))
         | ((unsigned)__half_as_ushort(__float2half_rn(f1)) << 16);
}
__device__ __forceinline__ void ldsm4(unsigned* r, unsigned a) {
    asm volatile("ldmatrix.sync.aligned.m8n8.x4.shared.b16 {%0,%1,%2,%3}, [%4];"
                 : "=r"(r[0]), "=r"(r[1]), "=r"(r[2]), "=r"(r[3]) : "r"(a));
}
__device__ __forceinline__ void mma16816(float* c, const unsigned* a, const unsigned* b) {
    asm volatile("mma.sync.aligned.m16n8k16.row.col.f32.f16.f16.f32 "
                 "{%0,%1,%2,%3}, {%4,%5,%6,%7}, {%8,%9}, {%0,%1,%2,%3};"
                 : "+f"(c[0]), "+f"(c[1]), "+f"(c[2]), "+f"(c[3])
                 : "r"(a[0]), "r"(a[1]), "r"(a[2]), "r"(a[3]), "r"(b[0]), "r"(b[1]));
}

// ---------------------------------------------------------------------------
__global__ void zero_kernel() {
    size_t idx = (size_t)blockIdx.x * blockDim.x + threadIdx.x;
    size_t n = (size_t)3 * B_ROWS * NCOLS;
    for (size_t i = idx; i < n; i += (size_t)gridDim.x * blockDim.x) g_acc[i] = 0.f;
    if (idx < 3 * B_ROWS * 8) g_scal[idx] = 0.f;
}

// ---------------------------------------------------------------------------
// One-pass prep: loads V,T tiles once; writes fp16 transposed planes
// (rows 0..255) AND gram/scal rows (256..263). grid = KPAD/32, block = 256.
__global__ void prep_all(const float* __restrict__ V, const float* __restrict__ T,
                         const float* __restrict__ W) {
    __shared__ float tv[32][129];
    __shared__ float tw[32][129];
    int k0 = blockIdx.x * 32, tid = threadIdx.x;
    // load tiles (zero-pad beyond K_TOTAL)
#pragma unroll
    for (int t = 0; t < 4; t++) {
        int idx = tid + t * 256;
        int r = idx >> 5, n4 = idx & 31;
        float4 v = make_float4(0.f, 0.f, 0.f, 0.f);
        float4 w = make_float4(0.f, 0.f, 0.f, 0.f);
        if (k0 + r < K_TOTAL) {
            v = *reinterpret_cast<const float4*>(V + (size_t)(k0 + r) * NFEAT + n4 * 4);
            w = *reinterpret_cast<const float4*>(T + (size_t)(k0 + r) * NFEAT + n4 * 4);
        }
        tv[r][n4*4+0] = v.x; tv[r][n4*4+1] = v.y; tv[r][n4*4+2] = v.z; tv[r][n4*4+3] = v.w;
        tw[r][n4*4+0] = w.x; tw[r][n4*4+1] = w.y; tw[r][n4*4+2] = w.z; tw[r][n4*4+3] = w.w;
    }
    __syncthreads();
    // gram rows: 32 rows, 8 warps -> 4 rows per warp
    int warp = tid >> 5, lane = tid & 31;
#pragma unroll
    for (int rr = 0; rr < 4; rr++) {
        int row = rr * 8 + warp;
        int k = k0 + row;
        float vv = 0.f, tts = 0.f, vt = 0.f;
#pragma unroll
        for (int j = 0; j < 4; j++) {
            float a = tv[row][lane * 4 + j], b = tw[row][lane * 4 + j];
            vv += a * a; tts += b * b; vt += a * b;
        }
#pragma unroll
        for (int o = 16; o; o >>= 1) {
            vv  += __shfl_down_sync(0xffffffffu, vv, o);
            tts += __shfl_down_sync(0xffffffffu, tts, o);
            vt  += __shfl_down_sync(0xffffffffu, vt, o);
        }
        if (lane == 0) {
            float wv = (k < K_TOTAL) ? W[k] : 0.f;
            float one = (k < K_TOTAL) ? 1.f : 0.f;
            BT16[(size_t)256 * KPAD + k] = __half_as_ushort(__float2half_rn(vv));
            BT16[(size_t)257 * KPAD + k] = __half_as_ushort(__float2half_rn(tts));
            BT16[(size_t)258 * KPAD + k] = __half_as_ushort(__float2half_rn(vt));
            BT16[(size_t)259 * KPAD + k] = __half_as_ushort(__float2half_rn(wv));
            BT16[(size_t)260 * KPAD + k] = __half_as_ushort(__float2half_rn(one));
            BT16[(size_t)261 * KPAD + k] = 0;
            BT16[(size_t)262 * KPAD + k] = 0;
            BT16[(size_t)263 * KPAD + k] = 0;
        }
    }
    // transpose writes: 1024 tasks = 2 mats x 128 n x 4 k-groups
#pragma unroll
    for (int t = 0; t < 4; t++) {
        int idx = tid + t * 256;
        int mat = idx >> 9, n = (idx >> 2) & 127, rq = idx & 3;
        int kk = k0 + rq * 8;
        unsigned hw[4];
#pragma unroll
        for (int j = 0; j < 4; j++) {
            float a = mat ? tw[rq*8 + 2*j][n]     : tv[rq*8 + 2*j][n];
            float b = mat ? tw[rq*8 + 2*j + 1][n] : tv[rq*8 + 2*j + 1][n];
            hw[j] = pack2h(a, b);
        }
        size_t off = (size_t)(mat * 128 + n) * KPAD + kk;
        *reinterpret_cast<uint4*>(BT16 + off) = make_uint4(hw[0], hw[1], hw[2], hw[3]);
    }
}

// ---------------------------------------------------------------------------
// CTA tile 128x256(+8 scal cols), 512 threads, 16 warps (4m x 4n), warp 32x64.
// Single fp16 product; scal columns via MMA on wc==0 warps.
// 3-stage ring, ONE __syncthreads per step. grid = (37, 16) = 592 = 4 waves.
// Stage: Ah @0 (16K) | B @16384 (33K: 264 rows x 128B, SW128).
__global__ void __launch_bounds__(NTHREADS, 1) gemm_kernel(
    const float* __restrict__ u, const float* __restrict__ xprev,
    const float* __restrict__ xpos, const float* __restrict__ xneg)
{
    extern __shared__ char dyn[];
    unsigned sraw = smem_u32(dyn);
    unsigned sb = (sraw + 1023u) & ~1023u;
    unsigned stg0 = sb, stg1 = sb + STAGE_SZ, stg2 = sb + 2 * STAGE_SZ;

    const int tid = threadIdx.x;
    const int lane = tid & 31, warp = tid >> 5;
    const int wr = warp >> 2, wc = warp & 3;   // 4m x 4n

    int kc = blockIdx.x;
    const float* A; int lda, kLen, segOff, accIdx, kStart;
    if (kc < 5)       { A = u;     lda = U_DIM; kLen = U_DIM; segOff = 0;             accIdx = 0; kStart = kc * 2000; }
    else if (kc < 15) { A = xprev; lda = X_DIM; kLen = X_DIM; segOff = U_DIM;         accIdx = 0; kStart = (kc - 5) * 2000; }
    else if (kc < 26) { A = xpos;  lda = X_DIM; kLen = X_DIM; segOff = U_DIM + X_DIM; accIdx = 1; kStart = (kc - 15) * 1824; }
    else              { A = xneg;  lda = X_DIM; kLen = X_DIM; segOff = U_DIM + X_DIM; accIdx = 2; kStart = (kc - 26) * 1824; }
    const int chunkLen = (kc < 15) ? 2000 : 1824;
    const int m0 = blockIdx.y * 128;
    const int kLenC = min(chunkLen, kLen - kStart);   // multiple of 16
    const int nsteps = (kLenC + KSTEP - 1) / KSTEP;

    // ---- B cp.async mapping: 2112 16B tasks -> 4/thread + 1 extra for tid<64 ----
    const unsigned short* bSrc[4]; unsigned bDst[4];
#pragma unroll
    for (int tt = 0; tt < 4; tt++) {
        int idx = tid + tt * NTHREADS;
        int rn = idx >> 3, kq = idx & 7;
        bSrc[tt] = BT16 + (size_t)rn * KPAD + segOff + kStart + kq * 8;
        unsigned off = rn * 128 + kq * 16;
        bDst[tt] = 16384u + (off ^ ((off >> 3) & 0x70));
    }
    const unsigned short* bSrcE = 0; unsigned bDstE = 0;
    if (tid < 64) {
        int idx = 2048 + tid;
        int rn = idx >> 3, kq = idx & 7;     // rn 256..263
        bSrcE = BT16 + (size_t)rn * KPAD + segOff + kStart + kq * 8;
        unsigned off = rn * 128 + kq * 16;
        bDstE = 16384u + (off ^ ((off >> 3) & 0x70));
    }
    // ---- A producer mapping: rows aRow0+{0,32,64,96}, 16 k-lanes ----
    const int aRow0 = tid >> 4, aC4 = tid & 15;
    const long l32 = (long)32 * lda;
    const float* aP0 = A + (size_t)(m0 + aRow0) * lda + kStart + aC4 * 4;
    const unsigned aSts0 = aRow0 * 128 + aC4 * 8;
    const unsigned aMsk = ((unsigned)(aRow0 & 7)) << 4;

    // ---- ldsm offsets (pre-swizzle) + masks ----
    unsigned aLd[2], aMk[2], bLd[4], bMk[4];
#pragma unroll
    for (int mi = 0; mi < 2; mi++) {
        int rowm = wr * 32 + mi * 16 + (lane & 15);
        aLd[mi] = rowm * 128 + (lane >> 4) * 16;
        aMk[mi] = ((unsigned)(rowm & 7)) << 4;
    }
#pragma unroll
    for (int nj = 0; nj < 4; nj++) {
        int rown = wc * 64 + nj * 16 + ((lane >> 4) << 3) + (lane & 7);
        bLd[nj] = rown * 128 + ((lane >> 3) & 1) * 16;
        bMk[nj] = ((unsigned)(rown & 7)) << 4;
    }
    const unsigned eLd = (unsigned)((256 + (lane & 7)) * 128
                         + ((lane >> 3) & 1) * 16 + (lane >> 4) * 32);
    const unsigned eMk = ((unsigned)(lane & 7)) << 4;

    float c[2][8][4];
#pragma unroll
    for (int i = 0; i < 2; i++)
#pragma unroll
        for (int j = 0; j < 8; j++)
#pragma unroll
            for (int q = 0; q < 4; q++) c[i][j][q] = 0.f;
    float ce[2][4];
#pragma unroll
    for (int i = 0; i < 2; i++)
#pragma unroll
        for (int q = 0; q < 4; q++) ce[i][q] = 0.f;
    unsigned be_[4];
    float4 avH[4];

#define ISSUE_B(st, bufAdr) do {                                                 \
    int bo_ = (st) * KSTEP;                                                      \
    _Pragma("unroll")                                                            \
    for (int tt = 0; tt < 4; tt++) {                                             \
        unsigned d_ = (bufAdr) + bDst[tt];                                       \
        const void* s_ = (const void*)(bSrc[tt] + bo_);                          \
        asm volatile("cp.async.cg.shared.global [%0], [%1], 16;"                 \
                     :: "r"(d_), "l"(s_) : "memory");                            \
    }                                                                            \
    if (tid < 64) {                                                              \
        unsigned d_ = (bufAdr) + bDstE;                                          \
        const void* s_ = (const void*)(bSrcE + bo_);                             \
        asm volatile("cp.async.cg.shared.global [%0], [%1], 16;"                 \
                     :: "r"(d_), "l"(s_) : "memory");                            \
    }                                                                            \
} while (0)

#define LDGA(stA) do {                                                           \
    int ko_ = (stA) * KSTEP + aC4 * 4;                                           \
    _Pragma("unroll")                                                            \
    for (int t = 0; t < 4; t++) {                                                \
        if (ko_ < kLenC)                                                         \
            avH[t] = *reinterpret_cast<const float4*>(aP0 + t * l32 + (stA) * KSTEP); \
        else avH[t] = make_float4(0.f, 0.f, 0.f, 0.f);                           \
    }                                                                            \
} while (0)

#define STSA(bufAdr) do {                                                        \
    _Pragma("unroll")                                                            \
    for (int t = 0; t < 4; t++) {                                                \
        unsigned h01 = pack2h(avH[t].x, avH[t].y);                               \
        unsigned h23 = pack2h(avH[t].z, avH[t].w);                               \
        unsigned o_ = (aSts0 + t * 4096u) ^ aMsk;                                \
        asm volatile("st.shared.v2.u32 [%0], {%1,%2};"                           \
                     :: "r"((bufAdr) + o_), "r"(h01), "r"(h23) : "memory");      \
    }                                                                            \
} while (0)

#define COMPUTE_KK(kk, bufAdr) do {                                              \
    unsigned bh_[4][4], ah_[2][4];                                               \
    _Pragma("unroll")                                                            \
    for (int nj = 0; nj < 4; nj++) {                                             \
        unsigned o_ = (bLd[nj] + (kk) * 32u) ^ bMk[nj];                          \
        ldsm4(bh_[nj], (bufAdr) + 16384u + o_);                                  \
    }                                                                            \
    _Pragma("unroll")                                                            \
    for (int mi = 0; mi < 2; mi++) {                                             \
        unsigned o_ = (aLd[mi] + (kk) * 32u) ^ aMk[mi];                          \
        ldsm4(ah_[mi], (bufAdr) + o_);                                           \
    }                                                                            \
    if (wc == 0 && ((kk) & 1) == 0) {                                            \
        unsigned o_ = (eLd + ((kk) >> 1) * 64u) ^ eMk;                           \
        ldsm4(be_, (bufAdr) + 16384u + o_);                                      \
    }                                                                            \
    _Pragma("unroll")                                                            \
    for (int mi = 0; mi < 2; mi++)                                               \
    _Pragma("unroll")                                                            \
    for (int nj = 0; nj < 4; nj++)                                               \
    _Pragma("unroll")                                                            \
    for (int h = 0; h < 2; h++) {                                                \
        mma16816(c[mi][nj * 2 + h], ah_[mi], &bh_[nj][h * 2]);                   \
    }                                                                            \
    if (wc == 0) {                                                               \
        _Pragma("unroll")                                                        \
        for (int mi = 0; mi < 2; mi++)                                           \
            mma16816(ce[mi], ah_[mi], &be_[((kk) & 1) * 2]);                     \
    }                                                                            \
} while (0)

    // ---- prologue: two B stages in flight ----
    ISSUE_B(0, stg0);
    asm volatile("cp.async.commit_group;" ::: "memory");
    if (nsteps > 1) ISSUE_B(1, stg1);
    asm volatile("cp.async.commit_group;" ::: "memory");
    LDGA(0);
    STSA(stg0);

    for (int st = 0; st < nsteps; st++) {
        asm volatile("cp.async.wait_group 1;" ::: "memory");
        __syncthreads();
        int r0i = st % 3;
        unsigned cur = (r0i == 0) ? stg0 : (r0i == 1) ? stg1 : stg2;
        unsigned nxt = (r0i == 0) ? stg1 : (r0i == 1) ? stg2 : stg0;
        unsigned nn2 = (r0i == 0) ? stg2 : (r0i == 1) ? stg0 : stg1;

        if (st + 2 < nsteps) ISSUE_B(st + 2, nn2);
        asm volatile("cp.async.commit_group;" ::: "memory");

        bool pf = (st + 1) < nsteps;
        if (pf) LDGA(st + 1);
        int kkEnd = min(4, (kLenC - st * KSTEP) >> 4);

        if (kkEnd == 4) {
            COMPUTE_KK(0, cur);
            COMPUTE_KK(1, cur);
            if (pf) STSA(nxt);
            COMPUTE_KK(2, cur);
            COMPUTE_KK(3, cur);
        } else {
            for (int kk = 0; kk < kkEnd; kk++) COMPUTE_KK(kk, cur);
        }
    }

    // ---- epilogue: atomic reduce C ----
    float* accBase = g_acc + (size_t)accIdx * B_ROWS * NCOLS;
#pragma unroll
    for (int mi = 0; mi < 2; mi++) {
        int r0 = m0 + wr * 32 + mi * 16 + (lane >> 2);
#pragma unroll
        for (int jj = 0; jj < 8; jj++) {
            int c0 = wc * 64 + jj * 8 + (lane & 3) * 2;
            atomicAdd(accBase + (size_t)r0 * NCOLS + c0,           c[mi][jj][0]);
            atomicAdd(accBase + (size_t)r0 * NCOLS + c0 + 1,       c[mi][jj][1]);
            atomicAdd(accBase + (size_t)(r0 + 8) * NCOLS + c0,     c[mi][jj][2]);
            atomicAdd(accBase + (size_t)(r0 + 8) * NCOLS + c0 + 1, c[mi][jj][3]);
        }
    }
    // ---- scal columns (wc==0 warps): cols {0..4} = z.{vv,tt,vt,W,1} ----
    if (wc == 0) {
        int c0 = (lane & 3) * 2;
#pragma unroll
        for (int mi = 0; mi < 2; mi++) {
            int r0 = m0 + wr * 32 + mi * 16 + (lane >> 2);
            float* d0 = g_scal + (size_t)(accIdx * B_ROWS + r0) * 8;
            float* d1 = g_scal + (size_t)(accIdx * B_ROWS + r0 + 8) * 8;
            if (c0 < 5)     { atomicAdd(d0 + c0,     ce[mi][0]); atomicAdd(d1 + c0,     ce[mi][2]); }
            if (c0 + 1 < 5) { atomicAdd(d0 + c0 + 1, ce[mi][1]); atomicAdd(d1 + c0 + 1, ce[mi][3]); }
        }
    }
#undef ISSUE_B
#undef LDGA
#undef STSA
#undef COMPUTE_KK
}

// ---------------------------------------------------------------------------
__global__ void final_kernel(const float* __restrict__ bias, float* __restrict__ out) {
    int warp = threadIdx.x >> 5, lane = threadIdx.x & 31;
    int row = blockIdx.x * 8 + warp;
    if (row >= B_ROWS) return;

    const float* aS = g_acc + (size_t)row * NCOLS;
    const float* aP = g_acc + ((size_t)B_ROWS + row) * NCOLS;
    const float* aN = g_acc + ((size_t)2 * B_ROWS + row) * NCOLS;

    float t5p = 0.f, t6p = 0.f, dgp = 0.f;
    float t5n = 0.f, t6n = 0.f, dgn = 0.f;
#pragma unroll
    for (int f = lane; f < NFEAT; f += 32) {
        float vs = aS[f],         vp = aP[f],         vn = aN[f];
        float ts = aS[NFEAT + f], tp = aP[NFEAT + f], tn = aN[NFEAT + f];
        float vxp = vs + vp, txp = ts + tp;
        float vxn = vs + vn, txn = ts + tn;
        t5p += vxp * vxp; t6p += txp * vxp; dgp += txp * txp;
        t5n += vxn * vxn; t6n += txn * vxn; dgn += txn * txn;
    }
#pragma unroll
    for (int o = 16; o; o >>= 1) {
        t5p += __shfl_down_sync(0xffffffffu, t5p, o);
        t6p += __shfl_down_sync(0xffffffffu, t6p, o);
        dgp += __shfl_down_sync(0xffffffffu, dgp, o);
        t5n += __shfl_down_sync(0xffffffffu, t5n, o);
        t6n += __shfl_down_sync(0xffffffffu, t6n, o);
        dgn += __shfl_down_sync(0xffffffffu, dgn, o);
    }
    if (lane == 0) {
        const float* sS = g_scal + (size_t)(0 * B_ROWS + row) * 8;
        const float* sP = g_scal + (size_t)(1 * B_ROWS + row) * 8;
        const float* sN = g_scal + (size_t)(2 * B_ROWS + row) * 8;

        float zvvp = sS[0] + sP[0], zttp = sS[1] + sP[1], zvtp = sS[2] + sP[2], zsp = sS[4] + sP[4];
        float zvvn = sS[0] + sN[0], zttn = sS[1] + sN[1], zvtn = sS[2] + sN[2], zsn = sS[4] + sN[4];
        float lin_neg = sS[3] + sN[3] + bias[0];

        float qp = 0.5f * (zsp * zvvp + 2.f * zsp * zttp + 2.f * zsp * zvtp
                           - 2.f * t5p - 2.f * t6p) - 0.5f * dgp;
        float qn = 0.5f * (zsn * zvvn + 2.f * zsn * zttn + 2.f * zsn * zvtn
                           - 2.f * t5n - 2.f * t6n) - 0.5f * dgn;

        out[row]          = lin_neg + qp;
        out[B_ROWS + row] = lin_neg + qn;
    }
}

// ---------------------------------------------------------------------------
extern "C" void kernel_launch(void* const* d_in, const int* in_sizes, int n_in,
                              void* d_out, int out_size) {
    const float* u     = (const float*)d_in[0];
    const float* xprev = (const float*)d_in[1];
    const float* xpos  = (const float*)d_in[2];
    const float* xneg  = (const float*)d_in[3];
    const float* V     = (const float*)d_in[4];
    const float* T     = (const float*)d_in[5];
    const float* W     = (const float*)d_in[6];
    const float* bias  = (const float*)d_in[7];
    float* out = (float*)d_out;

    cudaFuncSetAttribute(gemm_kernel, cudaFuncAttributeMaxDynamicSharedMemorySize, SMEM_DYN);

    zero_kernel<<<512, 256>>>();
    prep_all<<<KPAD / 32, 256>>>(V, T, W);
    gemm_kernel<<<dim3(37, 16), NTHREADS, SMEM_DYN>>>(u, xprev, xpos, xneg);
    final_kernel<<<B_ROWS / 8, 256>>>(bias, out);
}

// round 15
// speedup vs baseline: 1.0664x; 1.0664x over previous
#include <cuda_runtime.h>
#include <cuda_fp16.h>

// ---------------------------------------------------------------------------
#define B_ROWS   2048
#define NFEAT    128
#define NCOLS    256
#define NB_ROWS  264        // 256 V|T cols + 8 scal cols (vv,tt,vt,W,1,0,0,0)
#define K_TOTAL  50000
#define KPAD     50560      // multiple of 64, zero padded
#define U_DIM    10000
#define X_DIM    20000
#define KSTEP    64
#define STAGE_SZ 50176      // Ah 16K | B 33K (264 rows x 128B)
#define SMEM_DYN 101376     // 2 stages + 1KB align slack
#define NTHREADS 512

// ---------------------------------------------------------------------------
__device__ unsigned short BT16[(size_t)NB_ROWS * KPAD];  // fp16, K-major
__device__ float g_acc[(size_t)3 * B_ROWS * NCOLS];
__device__ float g_scal[3 * B_ROWS * 8];

// ---------------------------------------------------------------------------
__device__ __forceinline__ unsigned smem_u32(const void* p) {
    unsigned r;
    asm("{ .reg .u64 t; cvta.to.shared.u64 t, %1; cvt.u32.u64 %0, t; }" : "=r"(r) : "l"(p));
    return r;
}
__device__ __forceinline__ unsigned pack2h(float f0, float f1) {
    return (unsigned)__half_as_ushort(__float2half_rn(f0))
         | ((unsigned)__half_as_ushort(__float2half_rn(f1)) << 16);
}
__device__ __forceinline__ void ldsm4(unsigned* r, unsigned a) {
    asm volatile("ldmatrix.sync.aligned.m8n8.x4.shared.b16 {%0,%1,%2,%3}, [%4];"
                 : "=r"(r[0]), "=r"(r[1]), "=r"(r[2]), "=r"(r[3]) : "r"(a));
}
__device__ __forceinline__ void mma16816(float* c, const unsigned* a, const unsigned* b) {
    asm volatile("mma.sync.aligned.m16n8k16.row.col.f32.f16.f16.f32 "
                 "{%0,%1,%2,%3}, {%4,%5,%6,%7}, {%8,%9}, {%0,%1,%2,%3};"
                 : "+f"(c[0]), "+f"(c[1]), "+f"(c[2]), "+f"(c[3])
                 : "r"(a[0]), "r"(a[1]), "r"(a[2]), "r"(a[3]), "r"(b[0]), "r"(b[1]));
}

// ---------------------------------------------------------------------------
__global__ void zero_kernel() {
    size_t idx = (size_t)blockIdx.x * blockDim.x + threadIdx.x;
    size_t n = (size_t)3 * B_ROWS * NCOLS;
    for (size_t i = idx; i < n; i += (size_t)gridDim.x * blockDim.x) g_acc[i] = 0.f;
    if (idx < 3 * B_ROWS * 8) g_scal[idx] = 0.f;
}

// ---------------------------------------------------------------------------
// One-pass prep: loads V,T tiles once; writes fp16 transposed planes
// (rows 0..255) AND gram/scal rows (256..263). grid = KPAD/32, block = 256.
__global__ void prep_all(const float* __restrict__ V, const float* __restrict__ T,
                         const float* __restrict__ W) {
    __shared__ float tv[32][129];
    __shared__ float tw[32][129];
    int k0 = blockIdx.x * 32, tid = threadIdx.x;
#pragma unroll
    for (int t = 0; t < 4; t++) {
        int idx = tid + t * 256;
        int r = idx >> 5, n4 = idx & 31;
        float4 v = make_float4(0.f, 0.f, 0.f, 0.f);
        float4 w = make_float4(0.f, 0.f, 0.f, 0.f);
        if (k0 + r < K_TOTAL) {
            v = *reinterpret_cast<const float4*>(V + (size_t)(k0 + r) * NFEAT + n4 * 4);
            w = *reinterpret_cast<const float4*>(T + (size_t)(k0 + r) * NFEAT + n4 * 4);
        }
        tv[r][n4*4+0] = v.x; tv[r][n4*4+1] = v.y; tv[r][n4*4+2] = v.z; tv[r][n4*4+3] = v.w;
        tw[r][n4*4+0] = w.x; tw[r][n4*4+1] = w.y; tw[r][n4*4+2] = w.z; tw[r][n4*4+3] = w.w;
    }
    __syncthreads();
    int warp = tid >> 5, lane = tid & 31;
#pragma unroll
    for (int rr = 0; rr < 4; rr++) {
        int row = rr * 8 + warp;
        int k = k0 + row;
        float vv = 0.f, tts = 0.f, vt = 0.f;
#pragma unroll
        for (int j = 0; j < 4; j++) {
            float a = tv[row][lane * 4 + j], b = tw[row][lane * 4 + j];
            vv += a * a; tts += b * b; vt += a * b;
        }
#pragma unroll
        for (int o = 16; o; o >>= 1) {
            vv  += __shfl_down_sync(0xffffffffu, vv, o);
            tts += __shfl_down_sync(0xffffffffu, tts, o);
            vt  += __shfl_down_sync(0xffffffffu, vt, o);
        }
        if (lane == 0) {
            float wv = (k < K_TOTAL) ? W[k] : 0.f;
            float one = (k < K_TOTAL) ? 1.f : 0.f;
            BT16[(size_t)256 * KPAD + k] = __half_as_ushort(__float2half_rn(vv));
            BT16[(size_t)257 * KPAD + k] = __half_as_ushort(__float2half_rn(tts));
            BT16[(size_t)258 * KPAD + k] = __half_as_ushort(__float2half_rn(vt));
            BT16[(size_t)259 * KPAD + k] = __half_as_ushort(__float2half_rn(wv));
            BT16[(size_t)260 * KPAD + k] = __half_as_ushort(__float2half_rn(one));
            BT16[(size_t)261 * KPAD + k] = 0;
            BT16[(size_t)262 * KPAD + k] = 0;
            BT16[(size_t)263 * KPAD + k] = 0;
        }
    }
#pragma unroll
    for (int t = 0; t < 4; t++) {
        int idx = tid + t * 256;
        int mat = idx >> 9, n = (idx >> 2) & 127, rq = idx & 3;
        int kk = k0 + rq * 8;
        unsigned hw[4];
#pragma unroll
        for (int j = 0; j < 4; j++) {
            float a = mat ? tw[rq*8 + 2*j][n]     : tv[rq*8 + 2*j][n];
            float b = mat ? tw[rq*8 + 2*j + 1][n] : tv[rq*8 + 2*j + 1][n];
            hw[j] = pack2h(a, b);
        }
        size_t off = (size_t)(mat * 128 + n) * KPAD + kk;
        *reinterpret_cast<uint4*>(BT16 + off) = make_uint4(hw[0], hw[1], hw[2], hw[3]);
    }
}

// ---------------------------------------------------------------------------
// CTA tile 128x256(+8 scal cols), 512 threads, 16 warps (4m x 4n), warp 32x64.
// Single fp16 product; scal columns via MMA on wc==0 warps.
// R13 pipeline: 2 stages, two __syncthreads, B issued post-compute.
// grid = (37 kchunks, 16 mtiles) = 592 = 4 waves.
// Stage: Ah @0 (16K) | B @16384 (33K: 264 rows x 128B, SW128).
__global__ void __launch_bounds__(NTHREADS, 1) gemm_kernel(
    const float* __restrict__ u, const float* __restrict__ xprev,
    const float* __restrict__ xpos, const float* __restrict__ xneg)
{
    extern __shared__ char dyn[];
    unsigned sraw = smem_u32(dyn);
    unsigned sb = (sraw + 1023u) & ~1023u;
    const unsigned buf0 = sb, buf1 = sb + STAGE_SZ;

    const int tid = threadIdx.x;
    const int lane = tid & 31, warp = tid >> 5;
    const int wr = warp >> 2, wc = warp & 3;   // 4m x 4n

    int kc = blockIdx.x;
    const float* A; int lda, kLen, segOff, accIdx, kStart;
    if (kc < 5)       { A = u;     lda = U_DIM; kLen = U_DIM; segOff = 0;             accIdx = 0; kStart = kc * 2000; }
    else if (kc < 15) { A = xprev; lda = X_DIM; kLen = X_DIM; segOff = U_DIM;         accIdx = 0; kStart = (kc - 5) * 2000; }
    else if (kc < 26) { A = xpos;  lda = X_DIM; kLen = X_DIM; segOff = U_DIM + X_DIM; accIdx = 1; kStart = (kc - 15) * 1824; }
    else              { A = xneg;  lda = X_DIM; kLen = X_DIM; segOff = U_DIM + X_DIM; accIdx = 2; kStart = (kc - 26) * 1824; }
    const int chunkLen = (kc < 15) ? 2000 : 1824;
    const int m0 = blockIdx.y * 128;
    const int kLenC = min(chunkLen, kLen - kStart);   // multiple of 16
    const int nsteps = (kLenC + KSTEP - 1) / KSTEP;

    // ---- B cp.async mapping: 2112 16B tasks -> 4/thread + 1 extra for tid<64 ----
    const unsigned short* bSrc[4]; unsigned bDst[4];
#pragma unroll
    for (int tt = 0; tt < 4; tt++) {
        int idx = tid + tt * NTHREADS;
        int rn = idx >> 3, kq = idx & 7;
        bSrc[tt] = BT16 + (size_t)rn * KPAD + segOff + kStart + kq * 8;
        unsigned off = rn * 128 + kq * 16;
        bDst[tt] = 16384u + (off ^ ((off >> 3) & 0x70));
    }
    const unsigned short* bSrcE = 0; unsigned bDstE = 0;
    if (tid < 64) {
        int idx = 2048 + tid;
        int rn = idx >> 3, kq = idx & 7;     // rn 256..263
        bSrcE = BT16 + (size_t)rn * KPAD + segOff + kStart + kq * 8;
        unsigned off = rn * 128 + kq * 16;
        bDstE = 16384u + (off ^ ((off >> 3) & 0x70));
    }
    // ---- A producer mapping: rows aRow0+{0,32,64,96}, 16 k-lanes ----
    const int aRow0 = tid >> 4, aC4 = tid & 15;
    const long l32 = (long)32 * lda;
    const float* aP0 = A + (size_t)(m0 + aRow0) * lda + kStart + aC4 * 4;
    const unsigned aSts0 = aRow0 * 128 + aC4 * 8;
    const unsigned aMsk = ((unsigned)(aRow0 & 7)) << 4;

    // ---- ldsm offsets (pre-swizzle) + masks ----
    unsigned aLd[2], aMk[2], bLd[4], bMk[4];
#pragma unroll
    for (int mi = 0; mi < 2; mi++) {
        int rowm = wr * 32 + mi * 16 + (lane & 15);
        aLd[mi] = rowm * 128 + (lane >> 4) * 16;
        aMk[mi] = ((unsigned)(rowm & 7)) << 4;
    }
#pragma unroll
    for (int nj = 0; nj < 4; nj++) {
        int rown = wc * 64 + nj * 16 + ((lane >> 4) << 3) + (lane & 7);
        bLd[nj] = rown * 128 + ((lane >> 3) & 1) * 16;
        bMk[nj] = ((unsigned)(rown & 7)) << 4;
    }
    const unsigned eLd = (unsigned)((256 + (lane & 7)) * 128
                         + ((lane >> 3) & 1) * 16 + (lane >> 4) * 32);
    const unsigned eMk = ((unsigned)(lane & 7)) << 4;

    float c[2][8][4];
#pragma unroll
    for (int i = 0; i < 2; i++)
#pragma unroll
        for (int j = 0; j < 8; j++)
#pragma unroll
            for (int q = 0; q < 4; q++) c[i][j][q] = 0.f;
    float ce[2][4];
#pragma unroll
    for (int i = 0; i < 2; i++)
#pragma unroll
        for (int q = 0; q < 4; q++) ce[i][q] = 0.f;
    unsigned be_[4];
    float4 avH[4];

#define ISSUE_B(st, bufAdr) do {                                                 \
    int bo_ = (st) * KSTEP;                                                      \
    _Pragma("unroll")                                                            \
    for (int tt = 0; tt < 4; tt++) {                                             \
        unsigned d_ = (bufAdr) + bDst[tt];                                       \
        const void* s_ = (const void*)(bSrc[tt] + bo_);                          \
        asm volatile("cp.async.cg.shared.global [%0], [%1], 16;"                 \
                     :: "r"(d_), "l"(s_) : "memory");                            \
    }                                                                            \
    if (tid < 64) {                                                              \
        unsigned d_ = (bufAdr) + bDstE;                                          \
        const void* s_ = (const void*)(bSrcE + bo_);                             \
        asm volatile("cp.async.cg.shared.global [%0], [%1], 16;"                 \
                     :: "r"(d_), "l"(s_) : "memory");                            \
    }                                                                            \
} while (0)

#define LDGA(stA) do {                                                           \
    int ko_ = (stA) * KSTEP + aC4 * 4;                                           \
    _Pragma("unroll")                                                            \
    for (int t = 0; t < 4; t++) {                                                \
        if (ko_ < kLenC)                                                         \
            avH[t] = *reinterpret_cast<const float4*>(aP0 + t * l32 + (stA) * KSTEP); \
        else avH[t] = make_float4(0.f, 0.f, 0.f, 0.f);                           \
    }                                                                            \
} while (0)

#define STSA(bufAdr) do {                                                        \
    _Pragma("unroll")                                                            \
    for (int t = 0; t < 4; t++) {                                                \
        unsigned h01 = pack2h(avH[t].x, avH[t].y);                               \
        unsigned h23 = pack2h(avH[t].z, avH[t].w);                               \
        unsigned o_ = (aSts0 + t * 4096u) ^ aMsk;                                \
        asm volatile("st.shared.v2.u32 [%0], {%1,%2};"                           \
                     :: "r"((bufAdr) + o_), "r"(h01), "r"(h23) : "memory");      \
    }                                                                            \
} while (0)

#define COMPUTE_KK(kk, bufAdr) do {                                              \
    unsigned bh_[4][4], ah_[2][4];                                               \
    _Pragma("unroll")                                                            \
    for (int nj = 0; nj < 4; nj++) {                                             \
        unsigned o_ = (bLd[nj] + (kk) * 32u) ^ bMk[nj];                          \
        ldsm4(bh_[nj], (bufAdr) + 16384u + o_);                                  \
    }                                                                            \
    _Pragma("unroll")                                                            \
    for (int mi = 0; mi < 2; mi++) {                                             \
        unsigned o_ = (aLd[mi] + (kk) * 32u) ^ aMk[mi];                          \
        ldsm4(ah_[mi], (bufAdr) + o_);                                           \
    }                                                                            \
    if (wc == 0 && ((kk) & 1) == 0) {                                            \
        unsigned o_ = (eLd + ((kk) >> 1) * 64u) ^ eMk;                           \
        ldsm4(be_, (bufAdr) + 16384u + o_);                                      \
    }                                                                            \
    _Pragma("unroll")                                                            \
    for (int mi = 0; mi < 2; mi++)                                               \
    _Pragma("unroll")                                                            \
    for (int nj = 0; nj < 4; nj++)                                               \
    _Pragma("unroll")                                                            \
    for (int h = 0; h < 2; h++) {                                                \
        mma16816(c[mi][nj * 2 + h], ah_[mi], &bh_[nj][h * 2]);                   \
    }                                                                            \
    if (wc == 0) {                                                               \
        _Pragma("unroll")                                                        \
        for (int mi = 0; mi < 2; mi++)                                           \
            mma16816(ce[mi], ah_[mi], &be_[((kk) & 1) * 2]);                     \
    }                                                                            \
} while (0)

    // ---- prologue ----
    ISSUE_B(0, buf0);
    asm volatile("cp.async.commit_group;" ::: "memory");
    if (nsteps > 1) ISSUE_B(1, buf1);
    asm volatile("cp.async.commit_group;" ::: "memory");
    LDGA(0);
    STSA(buf0);

    for (int st = 0; st < nsteps; st++) {
        asm volatile("cp.async.wait_group 1;" ::: "memory");
        __syncthreads();
        unsigned bufC = (st & 1) ? buf1 : buf0;
        unsigned bufN = (st & 1) ? buf0 : buf1;
        bool pf = (st + 1) < nsteps;
        int kkEnd = min(4, (kLenC - st * KSTEP) >> 4);

        if (kkEnd == 4) {
            if (pf) LDGA(st + 1);
            COMPUTE_KK(0, bufC);
            COMPUTE_KK(1, bufC);
            if (pf) STSA(bufN);
            COMPUTE_KK(2, bufC);
            COMPUTE_KK(3, bufC);
        } else {
            for (int kk = 0; kk < kkEnd; kk++) COMPUTE_KK(kk, bufC);
        }
        __syncthreads();
        if (st + 2 < nsteps) ISSUE_B(st + 2, bufC);
        asm volatile("cp.async.commit_group;" ::: "memory");
    }

    // ---- epilogue: atomic reduce C ----
    float* accBase = g_acc + (size_t)accIdx * B_ROWS * NCOLS;
#pragma unroll
    for (int mi = 0; mi < 2; mi++) {
        int r0 = m0 + wr * 32 + mi * 16 + (lane >> 2);
#pragma unroll
        for (int jj = 0; jj < 8; jj++) {
            int c0 = wc * 64 + jj * 8 + (lane & 3) * 2;
            atomicAdd(accBase + (size_t)r0 * NCOLS + c0,           c[mi][jj][0]);
            atomicAdd(accBase + (size_t)r0 * NCOLS + c0 + 1,       c[mi][jj][1]);
            atomicAdd(accBase + (size_t)(r0 + 8) * NCOLS + c0,     c[mi][jj][2]);
            atomicAdd(accBase + (size_t)(r0 + 8) * NCOLS + c0 + 1, c[mi][jj][3]);
        }
    }
    // ---- scal columns (wc==0 warps): cols {0..4} = z.{vv,tt,vt,W,1} ----
    if (wc == 0) {
        int c0 = (lane & 3) * 2;
#pragma unroll
        for (int mi = 0; mi < 2; mi++) {
            int r0 = m0 + wr * 32 + mi * 16 + (lane >> 2);
            float* d0 = g_scal + (size_t)(accIdx * B_ROWS + r0) * 8;
            float* d1 = g_scal + (size_t)(accIdx * B_ROWS + r0 + 8) * 8;
            if (c0 < 5)     { atomicAdd(d0 + c0,     ce[mi][0]); atomicAdd(d1 + c0,     ce[mi][2]); }
            if (c0 + 1 < 5) { atomicAdd(d0 + c0 + 1, ce[mi][1]); atomicAdd(d1 + c0 + 1, ce[mi][3]); }
        }
    }
#undef ISSUE_B
#undef LDGA
#undef STSA
#undef COMPUTE_KK
}

// ---------------------------------------------------------------------------
__global__ void final_kernel(const float* __restrict__ bias, float* __restrict__ out) {
    int warp = threadIdx.x >> 5, lane = threadIdx.x & 31;
    int row = blockIdx.x * 8 + warp;
    if (row >= B_ROWS) return;

    const float* aS = g_acc + (size_t)row * NCOLS;
    const float* aP = g_acc + ((size_t)B_ROWS + row) * NCOLS;
    const float* aN = g_acc + ((size_t)2 * B_ROWS + row) * NCOLS;

    float t5p = 0.f, t6p = 0.f, dgp = 0.f;
    float t5n = 0.f, t6n = 0.f, dgn = 0.f;
#pragma unroll
    for (int f = lane; f < NFEAT; f += 32) {
        float vs = aS[f],         vp = aP[f],         vn = aN[f];
        float ts = aS[NFEAT + f], tp = aP[NFEAT + f], tn = aN[NFEAT + f];
        float vxp = vs + vp, txp = ts + tp;
        float vxn = vs + vn, txn = ts + tn;
        t5p += vxp * vxp; t6p += txp * vxp; dgp += txp * txp;
        t5n += vxn * vxn; t6n += txn * vxn; dgn += txn * txn;
    }
#pragma unroll
    for (int o = 16; o; o >>= 1) {
        t5p += __shfl_down_sync(0xffffffffu, t5p, o);
        t6p += __shfl_down_sync(0xffffffffu, t6p, o);
        dgp += __shfl_down_sync(0xffffffffu, dgp, o);
        t5n += __shfl_down_sync(0xffffffffu, t5n, o);
        t6n += __shfl_down_sync(0xffffffffu, t6n, o);
        dgn += __shfl_down_sync(0xffffffffu, dgn, o);
    }
    if (lane == 0) {
        const float* sS = g_scal + (size_t)(0 * B_ROWS + row) * 8;
        const float* sP = g_scal + (size_t)(1 * B_ROWS + row) * 8;
        const float* sN = g_scal + (size_t)(2 * B_ROWS + row) * 8;

        float zvvp = sS[0] + sP[0], zttp = sS[1] + sP[1], zvtp = sS[2] + sP[2], zsp = sS[4] + sP[4];
        float zvvn = sS[0] + sN[0], zttn = sS[1] + sN[1], zvtn = sS[2] + sN[2], zsn = sS[4] + sN[4];
        float lin_neg = sS[3] + sN[3] + bias[0];

        float qp = 0.5f * (zsp * zvvp + 2.f * zsp * zttp + 2.f * zsp * zvtp
                           - 2.f * t5p - 2.f * t6p) - 0.5f * dgp;
        float qn = 0.5f * (zsn * zvvn + 2.f * zsn * zttn + 2.f * zsn * zvtn
                           - 2.f * t5n - 2.f * t6n) - 0.5f * dgn;

        out[row]          = lin_neg + qp;
        out[B_ROWS + row] = lin_neg + qn;
    }
}

// ---------------------------------------------------------------------------
extern "C" void kernel_launch(void* const* d_in, const int* in_sizes, int n_in,
                              void* d_out, int out_size) {
    const float* u     = (const float*)d_in[0];
    const float* xprev = (const float*)d_in[1];
    const float* xpos  = (const float*)d_in[2];
    const float* xneg  = (const float*)d_in[3];
    const float* V     = (const float*)d_in[4];
    const float* T     = (const float*)d_in[5];
    const float* W     = (const float*)d_in[6];
    const float* bias  = (const float*)d_in[7];
    float* out = (float*)d_out;

    cudaFuncSetAttribute(gemm_kernel, cudaFuncAttributeMaxDynamicSharedMemorySize, SMEM_DYN);

    zero_kernel<<<512, 256>>>();
    prep_all<<<KPAD / 32, 256>>>(V, T, W);
    gemm_kernel<<<dim3(37, 16), NTHREADS, SMEM_DYN>>>(u, xprev, xpos, xneg);
    final_kernel<<<B_ROWS / 8, 256>>>(bias, out);
}